// round 4
// baseline (speedup 1.0000x reference)
#include <cuda_runtime.h>

// Problem constants
#define Nn   4
#define Pp   2048
#define Dd   512
#define Hh   8
#define HDim 64
#define NB   (Nn * Hh)                   // 32 batched (n,h) heads
#define SCALE 0.044194173824159216f      // 1/sqrt(512)  (reference scales by 1/sqrt(D), not 1/sqrt(HD))

// ---------------------------------------------------------------------------
// Device scratch (static globals: the sanctioned alloc-free scratch path)
// ---------------------------------------------------------------------------
__device__ float g_Q[(size_t)NB * Pp * HDim];     // [b][p][e], b = n*H+h
__device__ float g_K[(size_t)NB * Pp * HDim];
__device__ float g_V[(size_t)NB * Pp * HDim];
__device__ float g_OV[(size_t)Nn * Pp * Dd];      // attention @ V, (n,p,d) layout
__device__ float g_attn_fb[(size_t)NB * Pp * Pp]; // fallback if attention is not part of d_out

// ---------------------------------------------------------------------------
// K1: fused Q/K/V projection.
// Rows r = (n*P + p)*H + h  (65536 rows of 64).  x row = xyz + r*64.
// q[r][e] = sum_d x[r][d] * Wq[e][d]   -> g_Q[((n*H+h)*P + p)*64 + e]
// Block: 64 rows, 256 threads, each thread 4x4 outputs (strided by 16).
// ---------------------------------------------------------------------------
__global__ void __launch_bounds__(256) qkv_kernel(
    const float* __restrict__ x,
    const float* __restrict__ Wq,
    const float* __restrict__ Wk,
    const float* __restrict__ Wv)
{
    __shared__ float Xs[64][64];   // [row][d]   (reads are 2-addr broadcasts)
    __shared__ float Ws[64][65];   // [e][d]     (pad 65 -> conflict-free strided reads)

    const int t  = threadIdx.x;
    const int tx = t & 15;         // col group
    const int ty = t >> 4;         // row group
    const int r0 = blockIdx.x * 64;

    {
        const float4* src = reinterpret_cast<const float4*>(x) + (size_t)r0 * 16;
        float4* dst = reinterpret_cast<float4*>(&Xs[0][0]);
#pragma unroll
        for (int l = 0; l < 4; l++) dst[t + 256 * l] = src[t + 256 * l];
    }

#pragma unroll 1
    for (int m = 0; m < 3; m++) {
        const float* W = (m == 0) ? Wq : (m == 1) ? Wk : Wv;
        float*       O = (m == 0) ? g_Q : (m == 1) ? g_K : g_V;

        __syncthreads();  // Xs ready (m=0) / previous compute done (m>0)
#pragma unroll
        for (int l = 0; l < 16; l++) {
            int i = t + 256 * l;                 // 4096 scalars
            Ws[i >> 6][i & 63] = W[i];
        }
        __syncthreads();

        float acc[4][4];
#pragma unroll
        for (int i = 0; i < 4; i++)
#pragma unroll
            for (int j = 0; j < 4; j++) acc[i][j] = 0.f;

#pragma unroll 8
        for (int k = 0; k < 64; k++) {
            float a[4], w[4];
#pragma unroll
            for (int i = 0; i < 4; i++) a[i] = Xs[ty + 16 * i][k];
#pragma unroll
            for (int j = 0; j < 4; j++) w[j] = Ws[tx + 16 * j][k];
#pragma unroll
            for (int i = 0; i < 4; i++)
#pragma unroll
                for (int j = 0; j < 4; j++) acc[i][j] = fmaf(a[i], w[j], acc[i][j]);
        }

#pragma unroll
        for (int i = 0; i < 4; i++) {
            int r = r0 + ty + 16 * i;
            int h = r & 7;
            int p = (r >> 3) & (Pp - 1);
            int n = r >> 14;
            float* dst = O + ((size_t)(n * Hh + h) * Pp + p) * HDim;
#pragma unroll
            for (int j = 0; j < 4; j++) dst[tx + 16 * j] = acc[i][j];
        }
    }
}

// ---------------------------------------------------------------------------
// K2: energy = SCALE * Q_b (2048x64) @ K_b^T -> attn[b][q][k]  (raw logits)
// Block tile 128x128, 256 threads, strided 8x8 per thread, K staged 32 at a time.
// ---------------------------------------------------------------------------
__global__ void __launch_bounds__(256) qk_kernel(float* __restrict__ attn)
{
    __shared__ float Qs[128][33];  // [row][k], pad 33 (stride 1 mod 32 banks)
    __shared__ float Ks[128][33];

    const int t  = threadIdx.x;
    const int tx = t & 15;
    const int ty = t >> 4;
    const int b  = blockIdx.z;
    const int m0 = blockIdx.y * 128;
    const int n0 = blockIdx.x * 128;

    const float* Qg = g_Q + (size_t)b * Pp * HDim;
    const float* Kg = g_K + (size_t)b * Pp * HDim;

    float acc[8][8];
#pragma unroll
    for (int i = 0; i < 8; i++)
#pragma unroll
        for (int j = 0; j < 8; j++) acc[i][j] = 0.f;

#pragma unroll 1
    for (int kc = 0; kc < HDim; kc += 32) {
        __syncthreads();
#pragma unroll
        for (int l = 0; l < 4; l++) {
            int idx = t + 256 * l;               // 1024 float4 per matrix
            int c4  = idx & 7;                   // 8 float4 = 32 k per row
            int row = idx >> 3;                  // 0..127
            float4 q4 = *reinterpret_cast<const float4*>(
                Qg + (size_t)(m0 + row) * HDim + kc + c4 * 4);
            Qs[row][c4 * 4 + 0] = q4.x; Qs[row][c4 * 4 + 1] = q4.y;
            Qs[row][c4 * 4 + 2] = q4.z; Qs[row][c4 * 4 + 3] = q4.w;
            float4 k4 = *reinterpret_cast<const float4*>(
                Kg + (size_t)(n0 + row) * HDim + kc + c4 * 4);
            Ks[row][c4 * 4 + 0] = k4.x; Ks[row][c4 * 4 + 1] = k4.y;
            Ks[row][c4 * 4 + 2] = k4.z; Ks[row][c4 * 4 + 3] = k4.w;
        }
        __syncthreads();

#pragma unroll 8
        for (int k = 0; k < 32; k++) {
            float a[8], bb[8];
#pragma unroll
            for (int i = 0; i < 8; i++) a[i] = Qs[ty + 16 * i][k];
#pragma unroll
            for (int j = 0; j < 8; j++) bb[j] = Ks[tx + 16 * j][k];
#pragma unroll
            for (int i = 0; i < 8; i++)
#pragma unroll
                for (int j = 0; j < 8; j++) acc[i][j] = fmaf(a[i], bb[j], acc[i][j]);
        }
    }

    const size_t base = (size_t)b * Pp * Pp;
#pragma unroll
    for (int i = 0; i < 8; i++) {
        int row = m0 + ty + 16 * i;
        float* dst = attn + base + (size_t)row * Pp + n0;
#pragma unroll
        for (int j = 0; j < 8; j++) dst[tx + 16 * j] = acc[i][j] * SCALE;
    }
}

// ---------------------------------------------------------------------------
// K3: in-place row softmax over the last axis (2048). One block per row,
// the whole row lives in registers (8 floats/thread), one read + one write.
// ---------------------------------------------------------------------------
__global__ void __launch_bounds__(256) softmax_kernel(float* __restrict__ attn)
{
    __shared__ float red[8];
    const size_t row = blockIdx.x;
    float4* rp = reinterpret_cast<float4*>(attn + row * (size_t)Pp);
    const int t    = threadIdx.x;
    const int lane = t & 31;
    const int wid  = t >> 5;

    float4 a = rp[t];
    float4 b = rp[t + 256];

    float m = fmaxf(fmaxf(fmaxf(a.x, a.y), fmaxf(a.z, a.w)),
                    fmaxf(fmaxf(b.x, b.y), fmaxf(b.z, b.w)));
#pragma unroll
    for (int o = 16; o > 0; o >>= 1) m = fmaxf(m, __shfl_xor_sync(0xffffffffu, m, o));
    if (lane == 0) red[wid] = m;
    __syncthreads();
    float mb = red[0];
#pragma unroll
    for (int w = 1; w < 8; w++) mb = fmaxf(mb, red[w]);
    __syncthreads();                       // before reusing red[]

    a.x = __expf(a.x - mb); a.y = __expf(a.y - mb);
    a.z = __expf(a.z - mb); a.w = __expf(a.w - mb);
    b.x = __expf(b.x - mb); b.y = __expf(b.y - mb);
    b.z = __expf(b.z - mb); b.w = __expf(b.w - mb);

    float s = a.x + a.y + a.z + a.w + b.x + b.y + b.z + b.w;
#pragma unroll
    for (int o = 16; o > 0; o >>= 1) s += __shfl_xor_sync(0xffffffffu, s, o);
    if (lane == 0) red[wid] = s;
    __syncthreads();
    float sb = 0.f;
#pragma unroll
    for (int w = 0; w < 8; w++) sb += red[w];
    float inv = 1.0f / sb;

    a.x *= inv; a.y *= inv; a.z *= inv; a.w *= inv;
    b.x *= inv; b.y *= inv; b.z *= inv; b.w *= inv;
    rp[t] = a;
    rp[t + 256] = b;
}

// ---------------------------------------------------------------------------
// K4: out_v = attn_b (2048x2048) @ V_b (2048x64)  -> g_OV (n,p,d) layout.
// Block: 128 rows x 64 cols, 256 threads, 8x4 per thread, K staged 32.
// ---------------------------------------------------------------------------
__global__ void __launch_bounds__(256) av_kernel(const float* __restrict__ attn)
{
    __shared__ float As[128][33];
    __shared__ float Vs[32][64];

    const int t  = threadIdx.x;
    const int tx = t & 15;
    const int ty = t >> 4;
    const int b  = blockIdx.y;
    const int m0 = blockIdx.x * 128;

    const float* Ag = attn + (size_t)b * Pp * Pp;
    const float* Vg = g_V + (size_t)b * Pp * HDim;

    float acc[8][4];
#pragma unroll
    for (int i = 0; i < 8; i++)
#pragma unroll
        for (int j = 0; j < 4; j++) acc[i][j] = 0.f;

#pragma unroll 1
    for (int kc = 0; kc < Pp; kc += 32) {
        __syncthreads();
#pragma unroll
        for (int l = 0; l < 4; l++) {
            int idx = t + 256 * l;               // 1024 float4
            int c4  = idx & 7;
            int row = idx >> 3;
            float4 a4 = *reinterpret_cast<const float4*>(
                Ag + (size_t)(m0 + row) * Pp + kc + c4 * 4);
            As[row][c4 * 4 + 0] = a4.x; As[row][c4 * 4 + 1] = a4.y;
            As[row][c4 * 4 + 2] = a4.z; As[row][c4 * 4 + 3] = a4.w;
        }
#pragma unroll
        for (int l = 0; l < 2; l++) {
            int idx = t + 256 * l;               // 512 float4
            int c4  = idx & 15;
            int k   = idx >> 4;
            *reinterpret_cast<float4*>(&Vs[k][c4 * 4]) =
                *reinterpret_cast<const float4*>(Vg + (size_t)(kc + k) * HDim + c4 * 4);
        }
        __syncthreads();

#pragma unroll 8
        for (int k = 0; k < 32; k++) {
            float a[8], v[4];
#pragma unroll
            for (int i = 0; i < 8; i++) a[i] = As[ty + 16 * i][k];
#pragma unroll
            for (int j = 0; j < 4; j++) v[j] = Vs[k][tx + 16 * j];
#pragma unroll
            for (int i = 0; i < 8; i++)
#pragma unroll
                for (int j = 0; j < 4; j++) acc[i][j] = fmaf(a[i], v[j], acc[i][j]);
        }
    }

    const int n = b >> 3, h = b & 7;
#pragma unroll
    for (int i = 0; i < 8; i++) {
        int p = m0 + ty + 16 * i;
        float* dst = g_OV + ((size_t)n * Pp + p) * Dd + h * HDim;
#pragma unroll
        for (int j = 0; j < 4; j++) dst[tx + 16 * j] = acc[i][j];
    }
}

// ---------------------------------------------------------------------------
// K5: out = g_OV (8192x512) @ Wo^T + bo.  Tile 128x128, K staged 16.
// ---------------------------------------------------------------------------
__global__ void __launch_bounds__(256) wo_kernel(
    float* __restrict__ out,
    const float* __restrict__ Wo,
    const float* __restrict__ bo)
{
    __shared__ float Xs[128][17];
    __shared__ float Wos[128][17];

    const int t  = threadIdx.x;
    const int tx = t & 15;
    const int ty = t >> 4;
    const int m0 = blockIdx.y * 128;   // point rows (0..8191)
    const int n0 = blockIdx.x * 128;   // out cols  (0..511)

    float acc[8][8];
#pragma unroll
    for (int i = 0; i < 8; i++)
#pragma unroll
        for (int j = 0; j < 8; j++) acc[i][j] = 0.f;

#pragma unroll 1
    for (int kc = 0; kc < Dd; kc += 16) {
        __syncthreads();
#pragma unroll
        for (int l = 0; l < 2; l++) {
            int idx = t + 256 * l;               // 512 float4 per matrix
            int c4  = idx & 3;                   // 4 float4 = 16 k per row
            int row = idx >> 2;                  // 0..127
            float4 x4 = *reinterpret_cast<const float4*>(
                g_OV + (size_t)(m0 + row) * Dd + kc + c4 * 4);
            Xs[row][c4 * 4 + 0] = x4.x; Xs[row][c4 * 4 + 1] = x4.y;
            Xs[row][c4 * 4 + 2] = x4.z; Xs[row][c4 * 4 + 3] = x4.w;
            float4 w4 = *reinterpret_cast<const float4*>(
                Wo + (size_t)(n0 + row) * Dd + kc + c4 * 4);
            Wos[row][c4 * 4 + 0] = w4.x; Wos[row][c4 * 4 + 1] = w4.y;
            Wos[row][c4 * 4 + 2] = w4.z; Wos[row][c4 * 4 + 3] = w4.w;
        }
        __syncthreads();

#pragma unroll
        for (int k = 0; k < 16; k++) {
            float a[8], w[8];
#pragma unroll
            for (int i = 0; i < 8; i++) a[i] = Xs[ty + 16 * i][k];
#pragma unroll
            for (int j = 0; j < 8; j++) w[j] = Wos[tx + 16 * j][k];
#pragma unroll
            for (int i = 0; i < 8; i++)
#pragma unroll
                for (int j = 0; j < 8; j++) acc[i][j] = fmaf(a[i], w[j], acc[i][j]);
        }
    }

    float bv[8];
#pragma unroll
    for (int j = 0; j < 8; j++) bv[j] = bo[n0 + tx + 16 * j];

#pragma unroll
    for (int i = 0; i < 8; i++) {
        int row = m0 + ty + 16 * i;
#pragma unroll
        for (int j = 0; j < 8; j++)
            out[(size_t)row * Dd + n0 + tx + 16 * j] = acc[i][j] + bv[j];
    }
}

// ---------------------------------------------------------------------------
// Launch: 5 kernels on the capture stream; implicit ordering via same stream.
// ---------------------------------------------------------------------------
extern "C" void kernel_launch(void* const* d_in, const int* in_sizes, int n_in,
                              void* d_out, int out_size)
{
    const float* xyz = (const float*)d_in[0];
    const float* Wq  = (const float*)d_in[1];
    const float* Wk  = (const float*)d_in[2];
    const float* Wv  = (const float*)d_in[3];
    const float* Wo  = (const float*)d_in[4];
    const float* bo  = (const float*)d_in[5];
    float* out = (float*)d_out;

    const size_t OUT_E  = (size_t)Nn * Pp * Dd;         //   4,194,304
    const size_t ATTN_E = (size_t)NB * Pp * Pp;         // 134,217,728

    // Reference returns (out, attention): expect concatenated flat output.
    // Fall back to device scratch if the harness only checks `out`.
    float* attn;
    if ((size_t)out_size >= OUT_E + ATTN_E) {
        attn = out + OUT_E;
    } else {
        void* p = nullptr;
        cudaGetSymbolAddress(&p, g_attn_fb);
        attn = (float*)p;
    }

    qkv_kernel<<<(Nn * Pp * Hh) / 64, 256>>>(xyz, Wq, Wk, Wv);

    dim3 g2(Pp / 128, Pp / 128, NB);          // (16,16,32)
    qk_kernel<<<g2, 256>>>(attn);

    softmax_kernel<<<NB * Pp, 256>>>(attn);   // 65536 rows

    dim3 g4(Pp / 128, NB);                    // (16,32)
    av_kernel<<<g4, 256>>>(attn);

    dim3 g5(Dd / 128, (Nn * Pp) / 128);       // (4,64)
    wo_kernel<<<g5, 256>>>(out, Wo, bo);
}

// round 6
// speedup vs baseline: 1.1235x; 1.1235x over previous
#include <cuda_runtime.h>

// Problem constants
#define Nn   4
#define Pp   2048
#define Dd   512
#define Hh   8
#define HDim 64
#define NB   (Nn * Hh)                   // 32 batched (n,h) heads
#define SCALE 0.044194173824159216f      // 1/sqrt(512)

// ---------------------------------------------------------------------------
// Device scratch
// ---------------------------------------------------------------------------
__device__ float g_Q[(size_t)NB * Pp * HDim];     // [b][p][e], b = n*H+h
__device__ float g_K[(size_t)NB * Pp * HDim];
__device__ float g_V[(size_t)NB * Pp * HDim];
__device__ float g_OV[(size_t)Nn * Pp * Dd];      // attention @ V, (n,p,d)
__device__ float g_attn_fb[(size_t)NB * Pp * Pp]; // fallback attention buffer

// ---------------------------------------------------------------------------
// K1: fused Q/K/V projection (unchanged; ~30us).
// ---------------------------------------------------------------------------
__global__ void __launch_bounds__(256) qkv_kernel(
    const float* __restrict__ x,
    const float* __restrict__ Wq,
    const float* __restrict__ Wk,
    const float* __restrict__ Wv)
{
    __shared__ float Xs[64][64];
    __shared__ float Ws[64][65];

    const int t  = threadIdx.x;
    const int tx = t & 15;
    const int ty = t >> 4;
    const int r0 = blockIdx.x * 64;

    {
        const float4* src = reinterpret_cast<const float4*>(x) + (size_t)r0 * 16;
        float4* dst = reinterpret_cast<float4*>(&Xs[0][0]);
#pragma unroll
        for (int l = 0; l < 4; l++) dst[t + 256 * l] = src[t + 256 * l];
    }

#pragma unroll 1
    for (int m = 0; m < 3; m++) {
        const float* W = (m == 0) ? Wq : (m == 1) ? Wk : Wv;
        float*       O = (m == 0) ? g_Q : (m == 1) ? g_K : g_V;

        __syncthreads();
#pragma unroll
        for (int l = 0; l < 16; l++) {
            int i = t + 256 * l;
            Ws[i >> 6][i & 63] = W[i];
        }
        __syncthreads();

        float acc[4][4];
#pragma unroll
        for (int i = 0; i < 4; i++)
#pragma unroll
            for (int j = 0; j < 4; j++) acc[i][j] = 0.f;

#pragma unroll 8
        for (int k = 0; k < 64; k++) {
            float a[4], w[4];
#pragma unroll
            for (int i = 0; i < 4; i++) a[i] = Xs[ty + 16 * i][k];
#pragma unroll
            for (int j = 0; j < 4; j++) w[j] = Ws[tx + 16 * j][k];
#pragma unroll
            for (int i = 0; i < 4; i++)
#pragma unroll
                for (int j = 0; j < 4; j++) acc[i][j] = fmaf(a[i], w[j], acc[i][j]);
        }

#pragma unroll
        for (int i = 0; i < 4; i++) {
            int r = r0 + ty + 16 * i;
            int h = r & 7;
            int p = (r >> 3) & (Pp - 1);
            int n = r >> 14;
            float* dst = O + ((size_t)(n * Hh + h) * Pp + p) * HDim;
#pragma unroll
            for (int j = 0; j < 4; j++) dst[tx + 16 * j] = acc[i][j];
        }
    }
}

// ---------------------------------------------------------------------------
// K2: energy = (SCALE*Q_b) @ K_b^T.  128x128 tile, 256 threads, 8x8/thread.
// k-major smem tiles -> fragment loads are LDS.128 (4 LDS per 64 FMA).
// ---------------------------------------------------------------------------
__global__ void __launch_bounds__(256) qk_kernel(float* __restrict__ attn)
{
    __shared__ float Qs[32][128];   // [k][m]
    __shared__ float Ks[32][128];   // [k][n]

    const int t    = threadIdx.x;
    const int tx   = t & 15;        // col-fragment group
    const int ty   = t >> 4;        // row-fragment group
    const int row  = t & 127;       // load row
    const int half = t >> 7;        // load k-half (0: k 0..15, 1: k 16..31)
    const int b    = blockIdx.z;
    const int m0   = blockIdx.y * 128;
    const int n0   = blockIdx.x * 128;

    const float* Qg = g_Q + (size_t)b * Pp * HDim + (size_t)(m0 + row) * HDim + half * 16;
    const float* Kg = g_K + (size_t)b * Pp * HDim + (size_t)(n0 + row) * HDim + half * 16;

    float acc[8][8];
#pragma unroll
    for (int i = 0; i < 8; i++)
#pragma unroll
        for (int j = 0; j < 8; j++) acc[i][j] = 0.f;

#pragma unroll 1
    for (int kc = 0; kc < HDim; kc += 32) {
        __syncthreads();
#pragma unroll
        for (int j = 0; j < 4; j++) {
            float4 q4 = *reinterpret_cast<const float4*>(Qg + kc + j * 4);
            float4 k4 = *reinterpret_cast<const float4*>(Kg + kc + j * 4);
            int kk = half * 16 + j * 4;
            Qs[kk + 0][row] = q4.x * SCALE; Qs[kk + 1][row] = q4.y * SCALE;
            Qs[kk + 2][row] = q4.z * SCALE; Qs[kk + 3][row] = q4.w * SCALE;
            Ks[kk + 0][row] = k4.x; Ks[kk + 1][row] = k4.y;
            Ks[kk + 2][row] = k4.z; Ks[kk + 3][row] = k4.w;
        }
        __syncthreads();

#pragma unroll 16
        for (int k = 0; k < 32; k++) {
            float4 a0 = *reinterpret_cast<const float4*>(&Qs[k][ty * 4]);
            float4 a1 = *reinterpret_cast<const float4*>(&Qs[k][ty * 4 + 64]);
            float4 b0 = *reinterpret_cast<const float4*>(&Ks[k][tx * 4]);
            float4 b1 = *reinterpret_cast<const float4*>(&Ks[k][tx * 4 + 64]);
            float a[8]  = {a0.x, a0.y, a0.z, a0.w, a1.x, a1.y, a1.z, a1.w};
            float bb[8] = {b0.x, b0.y, b0.z, b0.w, b1.x, b1.y, b1.z, b1.w};
#pragma unroll
            for (int i = 0; i < 8; i++)
#pragma unroll
                for (int j = 0; j < 8; j++) acc[i][j] = fmaf(a[i], bb[j], acc[i][j]);
        }
    }

    float* dst = attn + (size_t)b * Pp * Pp;
#pragma unroll
    for (int i = 0; i < 8; i++) {
        int r = m0 + ty * 4 + (i & 3) + (i >> 2) * 64;
        float4 v0 = {acc[i][0], acc[i][1], acc[i][2], acc[i][3]};
        float4 v1 = {acc[i][4], acc[i][5], acc[i][6], acc[i][7]};
        *reinterpret_cast<float4*>(dst + (size_t)r * Pp + n0 + tx * 4)      = v0;
        *reinterpret_cast<float4*>(dst + (size_t)r * Pp + n0 + tx * 4 + 64) = v1;
    }
}

// ---------------------------------------------------------------------------
// K3: in-place row softmax (unchanged; ~memory-bound).
// ---------------------------------------------------------------------------
__global__ void __launch_bounds__(256) softmax_kernel(float* __restrict__ attn)
{
    __shared__ float red[8];
    const size_t row = blockIdx.x;
    float4* rp = reinterpret_cast<float4*>(attn + row * (size_t)Pp);
    const int t    = threadIdx.x;
    const int lane = t & 31;
    const int wid  = t >> 5;

    float4 a = rp[t];
    float4 b = rp[t + 256];

    float m = fmaxf(fmaxf(fmaxf(a.x, a.y), fmaxf(a.z, a.w)),
                    fmaxf(fmaxf(b.x, b.y), fmaxf(b.z, b.w)));
#pragma unroll
    for (int o = 16; o > 0; o >>= 1) m = fmaxf(m, __shfl_xor_sync(0xffffffffu, m, o));
    if (lane == 0) red[wid] = m;
    __syncthreads();
    float mb = red[0];
#pragma unroll
    for (int w = 1; w < 8; w++) mb = fmaxf(mb, red[w]);
    __syncthreads();

    a.x = __expf(a.x - mb); a.y = __expf(a.y - mb);
    a.z = __expf(a.z - mb); a.w = __expf(a.w - mb);
    b.x = __expf(b.x - mb); b.y = __expf(b.y - mb);
    b.z = __expf(b.z - mb); b.w = __expf(b.w - mb);

    float s = a.x + a.y + a.z + a.w + b.x + b.y + b.z + b.w;
#pragma unroll
    for (int o = 16; o > 0; o >>= 1) s += __shfl_xor_sync(0xffffffffu, s, o);
    if (lane == 0) red[wid] = s;
    __syncthreads();
    float sb = 0.f;
#pragma unroll
    for (int w = 0; w < 8; w++) sb += red[w];
    float inv = 1.0f / sb;

    a.x *= inv; a.y *= inv; a.z *= inv; a.w *= inv;
    b.x *= inv; b.y *= inv; b.z *= inv; b.w *= inv;
    rp[t] = a;
    rp[t + 256] = b;
}

// ---------------------------------------------------------------------------
// K4: out_v = attn_b (2048x2048) @ V_b (2048x64).
// 128x64 block tile, 128 threads, 8x8/thread, k staged 16 with register
// prefetch double buffering. k-major A tile -> LDS.128 fragments.
// ---------------------------------------------------------------------------
__global__ void __launch_bounds__(128, 4) av_kernel(const float* __restrict__ attn)
{
    __shared__ float As[16][128];   // [k][m]
    __shared__ float Vs[16][64];    // [k][n]

    const int t  = threadIdx.x;
    const int tx = t & 7;           // col-fragment group (8 groups x 8 cols)
    const int ty = t >> 3;          // row-fragment group (16 groups x 8 rows)
    const int b  = blockIdx.y;
    const int m0 = blockIdx.x * 128;

    const float* Ag = attn + (size_t)b * Pp * Pp + (size_t)(m0 + t) * Pp;
    const float* Vg = g_V + (size_t)b * Pp * HDim;

    // V-load mapping: 256 float4 per stage, 2 per thread
    const int vk0 = t >> 4,         vc0 = (t & 15) * 4;
    const int vk1 = (t + 128) >> 4, vc1 = ((t + 128) & 15) * 4;

    float acc[8][8];
#pragma unroll
    for (int i = 0; i < 8; i++)
#pragma unroll
        for (int j = 0; j < 8; j++) acc[i][j] = 0.f;

    float4 ra[4], rv0, rv1;
#pragma unroll
    for (int j = 0; j < 4; j++)
        ra[j] = *reinterpret_cast<const float4*>(Ag + j * 4);
    rv0 = *reinterpret_cast<const float4*>(Vg + (size_t)vk0 * HDim + vc0);
    rv1 = *reinterpret_cast<const float4*>(Vg + (size_t)vk1 * HDim + vc1);

#pragma unroll 1
    for (int kc = 0; kc < Pp; kc += 16) {
#pragma unroll
        for (int j = 0; j < 4; j++) {
            As[j * 4 + 0][t] = ra[j].x; As[j * 4 + 1][t] = ra[j].y;
            As[j * 4 + 2][t] = ra[j].z; As[j * 4 + 3][t] = ra[j].w;
        }
        *reinterpret_cast<float4*>(&Vs[vk0][vc0]) = rv0;
        *reinterpret_cast<float4*>(&Vs[vk1][vc1]) = rv1;
        __syncthreads();

        if (kc + 16 < Pp) {  // prefetch next stage behind the FMA block
#pragma unroll
            for (int j = 0; j < 4; j++)
                ra[j] = *reinterpret_cast<const float4*>(Ag + kc + 16 + j * 4);
            rv0 = *reinterpret_cast<const float4*>(Vg + (size_t)(kc + 16 + vk0) * HDim + vc0);
            rv1 = *reinterpret_cast<const float4*>(Vg + (size_t)(kc + 16 + vk1) * HDim + vc1);
        }

#pragma unroll
        for (int k = 0; k < 16; k++) {
            float4 a0 = *reinterpret_cast<const float4*>(&As[k][ty * 4]);
            float4 a1 = *reinterpret_cast<const float4*>(&As[k][ty * 4 + 64]);
            float4 v0 = *reinterpret_cast<const float4*>(&Vs[k][tx * 4]);
            float4 v1 = *reinterpret_cast<const float4*>(&Vs[k][tx * 4 + 32]);
            float a[8] = {a0.x, a0.y, a0.z, a0.w, a1.x, a1.y, a1.z, a1.w};
            float v[8] = {v0.x, v0.y, v0.z, v0.w, v1.x, v1.y, v1.z, v1.w};
#pragma unroll
            for (int i = 0; i < 8; i++)
#pragma unroll
                for (int j = 0; j < 8; j++) acc[i][j] = fmaf(a[i], v[j], acc[i][j]);
        }
        __syncthreads();
    }

    const int n = b >> 3, h = b & 7;
#pragma unroll
    for (int i = 0; i < 8; i++) {
        int p = m0 + ty * 4 + (i & 3) + (i >> 2) * 64;
        float* dst = g_OV + ((size_t)n * Pp + p) * Dd + h * HDim;
        float4 w0 = {acc[i][0], acc[i][1], acc[i][2], acc[i][3]};
        float4 w1 = {acc[i][4], acc[i][5], acc[i][6], acc[i][7]};
        *reinterpret_cast<float4*>(dst + tx * 4)      = w0;
        *reinterpret_cast<float4*>(dst + tx * 4 + 32) = w1;
    }
}

// ---------------------------------------------------------------------------
// K5: out = g_OV (8192x512) @ Wo^T + bo.  128x128 tile, 256 threads, 8x8,
// k staged 16, k-major smem, register prefetch.
// ---------------------------------------------------------------------------
__global__ void __launch_bounds__(256) wo_kernel(
    float* __restrict__ out,
    const float* __restrict__ Wo,
    const float* __restrict__ bo)
{
    __shared__ float Xs[16][128];   // [k][m]
    __shared__ float Ws[16][128];   // [k][n]

    const int t   = threadIdx.x;
    const int tx  = t & 15;
    const int ty  = t >> 4;
    const int m0  = blockIdx.y * 128;
    const int n0  = blockIdx.x * 128;
    const int lr  = t & 127;        // load row within the chosen matrix

    // warps 0-3 load X rows, warps 4-7 load Wo rows
    const float* src = (t < 128)
        ? g_OV + (size_t)(m0 + lr) * Dd
        : Wo   + (size_t)(n0 + lr) * Dd;
    float (*S)[128] = (t < 128) ? Xs : Ws;

    float acc[8][8];
#pragma unroll
    for (int i = 0; i < 8; i++)
#pragma unroll
        for (int j = 0; j < 8; j++) acc[i][j] = 0.f;

    float4 rg[4];
#pragma unroll
    for (int j = 0; j < 4; j++)
        rg[j] = *reinterpret_cast<const float4*>(src + j * 4);

#pragma unroll 1
    for (int kc = 0; kc < Dd; kc += 16) {
#pragma unroll
        for (int j = 0; j < 4; j++) {
            S[j * 4 + 0][lr] = rg[j].x; S[j * 4 + 1][lr] = rg[j].y;
            S[j * 4 + 2][lr] = rg[j].z; S[j * 4 + 3][lr] = rg[j].w;
        }
        __syncthreads();

        if (kc + 16 < Dd) {
#pragma unroll
            for (int j = 0; j < 4; j++)
                rg[j] = *reinterpret_cast<const float4*>(src + kc + 16 + j * 4);
        }

#pragma unroll
        for (int k = 0; k < 16; k++) {
            float4 a0 = *reinterpret_cast<const float4*>(&Xs[k][ty * 4]);
            float4 a1 = *reinterpret_cast<const float4*>(&Xs[k][ty * 4 + 64]);
            float4 w0 = *reinterpret_cast<const float4*>(&Ws[k][tx * 4]);
            float4 w1 = *reinterpret_cast<const float4*>(&Ws[k][tx * 4 + 64]);
            float a[8] = {a0.x, a0.y, a0.z, a0.w, a1.x, a1.y, a1.z, a1.w};
            float w[8] = {w0.x, w0.y, w0.z, w0.w, w1.x, w1.y, w1.z, w1.w};
#pragma unroll
            for (int i = 0; i < 8; i++)
#pragma unroll
                for (int j = 0; j < 8; j++) acc[i][j] = fmaf(a[i], w[j], acc[i][j]);
        }
        __syncthreads();
    }

    float bv[8];
#pragma unroll
    for (int j = 0; j < 8; j++)
        bv[j] = bo[n0 + tx * 4 + (j & 3) + (j >> 2) * 64];

#pragma unroll
    for (int i = 0; i < 8; i++) {
        int r = m0 + ty * 4 + (i & 3) + (i >> 2) * 64;
        float4 w0 = {acc[i][0] + bv[0], acc[i][1] + bv[1], acc[i][2] + bv[2], acc[i][3] + bv[3]};
        float4 w1 = {acc[i][4] + bv[4], acc[i][5] + bv[5], acc[i][6] + bv[6], acc[i][7] + bv[7]};
        *reinterpret_cast<float4*>(out + (size_t)r * Dd + n0 + tx * 4)      = w0;
        *reinterpret_cast<float4*>(out + (size_t)r * Dd + n0 + tx * 4 + 64) = w1;
    }
}

// ---------------------------------------------------------------------------
// Launch
// ---------------------------------------------------------------------------
extern "C" void kernel_launch(void* const* d_in, const int* in_sizes, int n_in,
                              void* d_out, int out_size)
{
    const float* xyz = (const float*)d_in[0];
    const float* Wq  = (const float*)d_in[1];
    const float* Wk  = (const float*)d_in[2];
    const float* Wv  = (const float*)d_in[3];
    const float* Wo  = (const float*)d_in[4];
    const float* bo  = (const float*)d_in[5];
    float* out = (float*)d_out;

    const size_t OUT_E  = (size_t)Nn * Pp * Dd;
    const size_t ATTN_E = (size_t)NB * Pp * Pp;

    float* attn;
    if ((size_t)out_size >= OUT_E + ATTN_E) {
        attn = out + OUT_E;
    } else {
        void* p = nullptr;
        cudaGetSymbolAddress(&p, g_attn_fb);
        attn = (float*)p;
    }

    qkv_kernel<<<(Nn * Pp * Hh) / 64, 256>>>(xyz, Wq, Wk, Wv);

    dim3 g2(Pp / 128, Pp / 128, NB);          // (16,16,32)
    qk_kernel<<<g2, 256>>>(attn);

    softmax_kernel<<<NB * Pp, 256>>>(attn);   // 65536 rows

    dim3 g4(Pp / 128, NB);                    // (16,32)
    av_kernel<<<g4, 128>>>(attn);

    dim3 g5(Dd / 128, (Nn * Pp) / 128);       // (4,64)
    wo_kernel<<<g5, 256>>>(out, Wo, bo);
}